// round 2
// baseline (speedup 1.0000x reference)
#include <cuda_runtime.h>

#define W 512
#define BAND_H 128
#define NBANDS 4
#define NIMG 96
#define VW 528   // 512 + 16 pad cols (zeroed), keeps float4 reads in-bounds

__device__ float g_partials[NBANDS * NIMG];

// horizontal 7-tap running sum: 8 outputs from 14 (staged 16) vsum values
__device__ __forceinline__ void hsum8(const float* rowp, int tx, float o[8]) {
    float f[16];
    const float4* v4 = reinterpret_cast<const float4*>(rowp + tx * 8);
#pragma unroll
    for (int i = 0; i < 4; i++) {
        float4 t = v4[i];
        f[4 * i + 0] = t.x; f[4 * i + 1] = t.y;
        f[4 * i + 2] = t.z; f[4 * i + 3] = t.w;
    }
    float s = f[0] + f[1] + f[2] + f[3] + f[4] + f[5] + f[6];
    o[0] = s;
#pragma unroll
    for (int k = 1; k < 8; k++) { s += f[k + 6] - f[k - 1]; o[k] = s; }
}

__global__ __launch_bounds__(256) void ssim_main(const float* __restrict__ img1,
                                                 const float* __restrict__ img2) {
    __shared__ __align__(16) float vsb[4][4][VW];  // [quantity][group-row][col]
    __shared__ float red[8];

    const int tid = threadIdx.x;
    const size_t base = (size_t)blockIdx.y * (W * W);
    const float* p1 = img1 + base;
    const float* p2 = img2 + base;
    const int r0 = 3 + blockIdx.x * BAND_H;
    const int rend = min(r0 + BAND_H, 509);

    // zero the pad columns [512,528) for all 16 (q,g) rows — one element per thread
    {
        int q = tid >> 6, g = (tid >> 4) & 3, c = 512 + (tid & 15);
        vsb[q][g][c] = 0.f;
    }

    const int c0 = tid * 2;
    const float inv = 1.0f / 49.0f;
    const float CN  = 49.0f / 48.0f;
    const float C1  = 1e-4f, C2 = 9e-4f;
    float acc = 0.f;

    for (int r = r0; r < rend; r += 4) {
        // ---- Phase A: vertical 7-sums for 4 output rows, 2 cols/thread ----
        float2 Sx[4], Sy[4], Sp[4], Ss[4];
#pragma unroll
        for (int g = 0; g < 4; g++) {
            Sx[g] = make_float2(0.f, 0.f); Sy[g] = make_float2(0.f, 0.f);
            Sp[g] = make_float2(0.f, 0.f); Ss[g] = make_float2(0.f, 0.f);
        }
#pragma unroll
        for (int dr = -3; dr <= 6; dr++) {
            int rin = r + dr;                       // rin >= r0-3 >= 0 always
            float2 a = make_float2(0.f, 0.f), b = make_float2(0.f, 0.f);
            if (rin < W) {
                a = reinterpret_cast<const float2*>(p1 + (size_t)rin * W)[tid];
                b = reinterpret_cast<const float2*>(p2 + (size_t)rin * W)[tid];
            }
            float2 pp, ps;
            pp.x = a.x * b.x;              pp.y = a.y * b.y;
            ps.x = a.x * a.x + b.x * b.x;  ps.y = a.y * a.y + b.y * b.y;
#pragma unroll
            for (int g = 0; g < 4; g++) {
                if (dr >= g - 3 && dr <= g + 3) {   // compile-time pruned
                    Sx[g].x += a.x;  Sx[g].y += a.y;
                    Sy[g].x += b.x;  Sy[g].y += b.y;
                    Sp[g].x += pp.x; Sp[g].y += pp.y;
                    Ss[g].x += ps.x; Ss[g].y += ps.y;
                }
            }
        }
#pragma unroll
        for (int g = 0; g < 4; g++) {
            *reinterpret_cast<float2*>(&vsb[0][g][c0]) = Sx[g];
            *reinterpret_cast<float2*>(&vsb[1][g][c0]) = Sy[g];
            *reinterpret_cast<float2*>(&vsb[2][g][c0]) = Sp[g];
            *reinterpret_cast<float2*>(&vsb[3][g][c0]) = Ss[g];
        }
        __syncthreads();

        // ---- Phase B: horizontal 7-sums + SSIM map + accumulate ----
        {
            const int ty = tid >> 6, tx = tid & 63;
            const int rout = r + ty;
            if (rout < rend) {
                float ox[8], oy[8], op[8], os[8];
                hsum8(vsb[0][ty], tx, ox);
                hsum8(vsb[1][ty], tx, oy);
                hsum8(vsb[2][ty], tx, op);
                hsum8(vsb[3][ty], tx, os);
                const int cbase = 3 + tx * 8;
#pragma unroll
                for (int k = 0; k < 8; k++) {
                    float ux  = ox[k] * inv;
                    float uy  = oy[k] * inv;
                    float uxy = op[k] * inv;
                    float uss = os[k] * inv;
                    float uxuy = ux * uy;
                    float sq   = ux * ux + uy * uy;
                    float A1 = 2.f * uxuy + C1;
                    float A2 = 2.f * CN * (uxy - uxuy) + C2;
                    float B1 = sq + C1;
                    float B2 = CN * (uss - sq) + C2;
                    float S = __fdividef(A1 * A2, B1 * B2);
                    if (cbase + k <= 508) acc += S;
                }
            }
        }
        __syncthreads();
    }

    // ---- block reduction ----
#pragma unroll
    for (int o = 16; o > 0; o >>= 1) acc += __shfl_down_sync(0xFFFFFFFFu, acc, o);
    if ((tid & 31) == 0) red[tid >> 5] = acc;
    __syncthreads();
    if (tid == 0) {
        float t = 0.f;
#pragma unroll
        for (int i = 0; i < 8; i++) t += red[i];
        g_partials[blockIdx.y * NBANDS + blockIdx.x] = t;
    }
}

__global__ void ssim_reduce(float* __restrict__ out) {
    __shared__ double red[12];
    const int tid = threadIdx.x;  // 384 threads
    double v = (double)g_partials[tid];
#pragma unroll
    for (int o = 16; o > 0; o >>= 1) v += __shfl_down_sync(0xFFFFFFFFu, v, o);
    if ((tid & 31) == 0) red[tid >> 5] = v;
    __syncthreads();
    if (tid == 0) {
        double t = 0.0;
#pragma unroll
        for (int i = 0; i < 12; i++) t += red[i];
        out[0] = (float)(t / (96.0 * 506.0 * 506.0));
    }
}

extern "C" void kernel_launch(void* const* d_in, const int* in_sizes, int n_in,
                              void* d_out, int out_size) {
    const float* img1 = (const float*)d_in[0];
    const float* img2 = (const float*)d_in[1];
    dim3 grid(NBANDS, NIMG);
    ssim_main<<<grid, 256>>>(img1, img2);
    ssim_reduce<<<1, NBANDS * NIMG>>>((float*)d_out);
}

// round 3
// speedup vs baseline: 1.1334x; 1.1334x over previous
#include <cuda_runtime.h>

#define W 512
#define BAND_H 64
#define NBANDS 8
#define NIMG 96
#define VW 528   // 512 + 16 pad cols (zeroed), keeps float4 reads in-bounds

__device__ float g_partials[NBANDS * NIMG];

__device__ __forceinline__ float2 ldrow(const float* __restrict__ p, int row, int tid) {
    return reinterpret_cast<const float2*>(p + (size_t)row * W)[tid];
}

// horizontal 7-tap running sum: 8 outputs from 14 (staged 16) vsum values
__device__ __forceinline__ void hsum8(const float* rowp, int tx, float o[8]) {
    float f[16];
    const float4* v4 = reinterpret_cast<const float4*>(rowp + tx * 8);
#pragma unroll
    for (int i = 0; i < 4; i++) {
        float4 t = v4[i];
        f[4 * i + 0] = t.x; f[4 * i + 1] = t.y;
        f[4 * i + 2] = t.z; f[4 * i + 3] = t.w;
    }
    float s = f[0] + f[1] + f[2] + f[3] + f[4] + f[5] + f[6];
    o[0] = s;
#pragma unroll
    for (int k = 1; k < 8; k++) { s += f[k + 6] - f[k - 1]; o[k] = s; }
}

__global__ __launch_bounds__(256) void ssim_main(const float* __restrict__ img1,
                                                 const float* __restrict__ img2) {
    __shared__ __align__(16) float vsb[4][4][VW];  // [quantity][group-row][col]
    __shared__ float red[8];

    const int tid = threadIdx.x;
    const size_t base = (size_t)blockIdx.y * (W * W);
    const float* p1 = img1 + base;
    const float* p2 = img2 + base;
    const int r0 = 3 + blockIdx.x * BAND_H;
    const int rend = min(r0 + BAND_H, 509);

    // zero the pad columns [512,528) for all 16 (q,g) rows — one element per thread
    {
        int q = tid >> 6, g = (tid >> 4) & 3, c = 512 + (tid & 15);
        vsb[q][g][c] = 0.f;
    }

    const float inv = 1.0f / 49.0f;
    const float CN  = 49.0f / 48.0f;
    const float C1  = 1e-4f, C2 = 9e-4f;
    const int c0 = tid * 2;
    float acc = 0.f;

    // ---- prime sliding vertical sums with rows r0-3 .. r0+2 (all >= 0) ----
    float2 Sx = make_float2(0.f, 0.f), Sy = make_float2(0.f, 0.f);
    float2 Sp = make_float2(0.f, 0.f), Ss = make_float2(0.f, 0.f);
#pragma unroll
    for (int dr = -3; dr <= 2; dr++) {
        float2 a = ldrow(p1, r0 + dr, tid);
        float2 b = ldrow(p2, r0 + dr, tid);
        Sx.x += a.x; Sx.y += a.y;
        Sy.x += b.x; Sy.y += b.y;
        Sp.x = fmaf(a.x, b.x, Sp.x); Sp.y = fmaf(a.y, b.y, Sp.y);
        Ss.x = fmaf(a.x, a.x, fmaf(b.x, b.x, Ss.x));
        Ss.y = fmaf(a.y, a.y, fmaf(b.y, b.y, Ss.y));
    }

    for (int r = r0; r < rend; r += 4) {
        // ---- Phase A: slide vertical window, one row per g ----
#pragma unroll
        for (int g = 0; g < 4; g++) {
            const int row = r + g;
            if (row < rend) {                       // uniform across block
                {   // entering row: row+3 <= 511
                    float2 a = ldrow(p1, row + 3, tid);
                    float2 b = ldrow(p2, row + 3, tid);
                    Sx.x += a.x; Sx.y += a.y;
                    Sy.x += b.x; Sy.y += b.y;
                    Sp.x = fmaf(a.x, b.x, Sp.x); Sp.y = fmaf(a.y, b.y, Sp.y);
                    Ss.x = fmaf(a.x, a.x, fmaf(b.x, b.x, Ss.x));
                    Ss.y = fmaf(a.y, a.y, fmaf(b.y, b.y, Ss.y));
                }
                if (row > r0) {                     // exiting row: row-4 >= r0-3 >= 0
                    float2 a = ldrow(p1, row - 4, tid);
                    float2 b = ldrow(p2, row - 4, tid);
                    Sx.x -= a.x; Sx.y -= a.y;
                    Sy.x -= b.x; Sy.y -= b.y;
                    Sp.x = fmaf(-a.x, b.x, Sp.x); Sp.y = fmaf(-a.y, b.y, Sp.y);
                    Ss.x = fmaf(-a.x, a.x, fmaf(-b.x, b.x, Ss.x));
                    Ss.y = fmaf(-a.y, a.y, fmaf(-b.y, b.y, Ss.y));
                }
                *reinterpret_cast<float2*>(&vsb[0][g][c0]) = Sx;
                *reinterpret_cast<float2*>(&vsb[1][g][c0]) = Sy;
                *reinterpret_cast<float2*>(&vsb[2][g][c0]) = Sp;
                *reinterpret_cast<float2*>(&vsb[3][g][c0]) = Ss;
            }
        }
        __syncthreads();

        // ---- Phase B: horizontal 7-sums + SSIM map + accumulate ----
        {
            const int ty = tid >> 6, tx = tid & 63;
            const int rout = r + ty;
            if (rout < rend) {
                float ox[8], oy[8], op[8], os[8];
                hsum8(vsb[0][ty], tx, ox);
                hsum8(vsb[1][ty], tx, oy);
                hsum8(vsb[2][ty], tx, op);
                hsum8(vsb[3][ty], tx, os);
                const int cbase = 3 + tx * 8;
#pragma unroll
                for (int k = 0; k < 8; k++) {
                    float ux  = ox[k] * inv;
                    float uy  = oy[k] * inv;
                    float uxy = op[k] * inv;
                    float uss = os[k] * inv;
                    float uxuy = ux * uy;
                    float sq   = ux * ux + uy * uy;
                    float A1 = 2.f * uxuy + C1;
                    float A2 = 2.f * CN * (uxy - uxuy) + C2;
                    float B1 = sq + C1;
                    float B2 = CN * (uss - sq) + C2;
                    float S = __fdividef(A1 * A2, B1 * B2);
                    if (cbase + k <= 508) acc += S;
                }
            }
        }
        __syncthreads();
    }

    // ---- block reduction ----
#pragma unroll
    for (int o = 16; o > 0; o >>= 1) acc += __shfl_down_sync(0xFFFFFFFFu, acc, o);
    if ((tid & 31) == 0) red[tid >> 5] = acc;
    __syncthreads();
    if (tid == 0) {
        float t = 0.f;
#pragma unroll
        for (int i = 0; i < 8; i++) t += red[i];
        g_partials[blockIdx.y * NBANDS + blockIdx.x] = t;
    }
}

__global__ void ssim_reduce(float* __restrict__ out) {
    __shared__ double red[24];
    const int tid = threadIdx.x;  // 768 threads
    double v = (double)g_partials[tid];
#pragma unroll
    for (int o = 16; o > 0; o >>= 1) v += __shfl_down_sync(0xFFFFFFFFu, v, o);
    if ((tid & 31) == 0) red[tid >> 5] = v;
    __syncthreads();
    if (tid == 0) {
        double t = 0.0;
#pragma unroll
        for (int i = 0; i < 24; i++) t += red[i];
        out[0] = (float)(t / (96.0 * 506.0 * 506.0));
    }
}

extern "C" void kernel_launch(void* const* d_in, const int* in_sizes, int n_in,
                              void* d_out, int out_size) {
    const float* img1 = (const float*)d_in[0];
    const float* img2 = (const float*)d_in[1];
    dim3 grid(NBANDS, NIMG);
    ssim_main<<<grid, 256>>>(img1, img2);
    ssim_reduce<<<1, NBANDS * NIMG>>>((float*)d_out);
}

// round 4
// speedup vs baseline: 1.3458x; 1.1874x over previous
#include <cuda_runtime.h>

#define W 512
#define BAND_H 64
#define NBANDS 8
#define NIMG 96
#define VW 528
#define ROWB (VW * 8)   // 4224 bytes per (qpair, g) shared row; 4224 = 33*128 (window-aligned)

typedef unsigned long long u64;

__device__ float g_partials[NBANDS * NIMG];

__device__ __forceinline__ u64 f2pack(float x, float y) {
    u64 d; asm("mov.b64 %0, {%1, %2};" : "=l"(d) : "f"(x), "f"(y)); return d;
}
__device__ __forceinline__ void f2unpack(u64 a, float& x, float& y) {
    asm("mov.b64 {%0, %1}, %2;" : "=f"(x), "=f"(y) : "l"(a));
}
__device__ __forceinline__ u64 f2add(u64 a, u64 b) {
    u64 d; asm("add.rn.f32x2 %0, %1, %2;" : "=l"(d) : "l"(a), "l"(b)); return d;
}
__device__ __forceinline__ u64 f2mul(u64 a, u64 b) {
    u64 d; asm("mul.rn.f32x2 %0, %1, %2;" : "=l"(d) : "l"(a), "l"(b)); return d;
}
__device__ __forceinline__ u64 f2fma(u64 a, u64 b, u64 c) {
    u64 d; asm("fma.rn.f32x2 %0, %1, %2, %3;" : "=l"(d) : "l"(a), "l"(b), "l"(c)); return d;
}
__device__ __forceinline__ u64 f2neg(u64 a) { return a ^ 0x8000000080000000ULL; }

// 16B-block swizzle: XOR bits[8:7] into bits[5:4]. Conflict-free for both the
// 16B-stride writes and the 64B-stride float4 reads (verified by enumeration).
__device__ __forceinline__ int sw(int o) { return o ^ (((o >> 7) & 3) << 4); }

__device__ __forceinline__ float2 ldrow(const float* __restrict__ p, int row, int tid) {
    return reinterpret_cast<const float2*>(p + (size_t)row * W)[tid];
}

__global__ __launch_bounds__(256) void ssim_main(const float* __restrict__ img1,
                                                 const float* __restrict__ img2) {
    // rows 0..3: (x,y) interleaved pairs for g=0..3 ; rows 4..7: (p,ss) pairs
    __shared__ __align__(16) char vs[8 * ROWB];
    __shared__ float red[8];

    const int tid = threadIdx.x;
    const size_t base = (size_t)blockIdx.y * (W * W);
    const float* p1 = img1 + base;
    const float* p2 = img2 + base;
    const int r0 = 3 + blockIdx.x * BAND_H;
    const int rend = min(r0 + BAND_H, 509);

    // zero pad blocks (cols 512..527 = blocks 256..263) for all 8 shared rows
    if (tid < 64) {
        int rowi = tid >> 3, b = 256 + (tid & 7);
        *reinterpret_cast<float4*>(vs + rowi * ROWB + sw(b * 16)) =
            make_float4(0.f, 0.f, 0.f, 0.f);
    }

    // scale-folded constants (multiply A/B terms by 49^2; ratio unchanged)
    const float CNf = 49.0f / 48.0f;
    const u64 c1_2    = f2pack(1e-4f * 2401.0f, 1e-4f * 2401.0f);
    const u64 c2_2    = f2pack(9e-4f * 2401.0f, 9e-4f * 2401.0f);
    const u64 two_2   = f2pack(2.0f, 2.0f);
    const u64 k2cn49  = f2pack(2.0f * CNf * 49.0f, 2.0f * CNf * 49.0f);
    const u64 nk2cn   = f2pack(-2.0f * CNf, -2.0f * CNf);
    const u64 kcn49   = f2pack(CNf * 49.0f, CNf * 49.0f);
    const u64 nkcn    = f2pack(-CNf, -CNf);

    float acc = 0.f;

    // ---- prime sliding vertical sums with rows r0-3 .. r0+2 ----
    u64 Sx = 0, Sy = 0, Sp = 0, Ss = 0;
#pragma unroll
    for (int dr = -3; dr <= 2; dr++) {
        float2 a = ldrow(p1, r0 + dr, tid);
        float2 b = ldrow(p2, r0 + dr, tid);
        u64 a2 = f2pack(a.x, a.y), b2 = f2pack(b.x, b.y);
        Sx = f2add(Sx, a2);
        Sy = f2add(Sy, b2);
        Sp = f2fma(a2, b2, Sp);
        Ss = f2fma(a2, a2, Ss);
        Ss = f2fma(b2, b2, Ss);
    }

    for (int r = r0; r < rend; r += 4) {
        // ---- Phase A: slide vertical window, one row per g ----
#pragma unroll
        for (int g = 0; g < 4; g++) {
            const int row = r + g;
            if (row < rend) {                       // uniform across block
                {   // entering row (row+3 <= 511)
                    float2 a = ldrow(p1, row + 3, tid);
                    float2 b = ldrow(p2, row + 3, tid);
                    u64 a2 = f2pack(a.x, a.y), b2 = f2pack(b.x, b.y);
                    Sx = f2add(Sx, a2);
                    Sy = f2add(Sy, b2);
                    Sp = f2fma(a2, b2, Sp);
                    Ss = f2fma(a2, a2, Ss);
                    Ss = f2fma(b2, b2, Ss);
                }
                if (row > r0) {                     // exiting row (row-4 >= 0)
                    float2 a = ldrow(p1, row - 4, tid);
                    float2 b = ldrow(p2, row - 4, tid);
                    u64 a2 = f2pack(a.x, a.y), b2 = f2pack(b.x, b.y);
                    u64 na = f2neg(a2), nb = f2neg(b2);
                    Sx = f2add(Sx, na);
                    Sy = f2add(Sy, nb);
                    Sp = f2fma(na, b2, Sp);
                    Ss = f2fma(na, a2, Ss);
                    Ss = f2fma(nb, b2, Ss);
                }
                float sx0, sx1, sy0, sy1, sp0, sp1, ss0, ss1;
                f2unpack(Sx, sx0, sx1); f2unpack(Sy, sy0, sy1);
                f2unpack(Sp, sp0, sp1); f2unpack(Ss, ss0, ss1);
                const int o = sw(tid * 16);
                *reinterpret_cast<float4*>(vs + g * ROWB + o) =
                    make_float4(sx0, sy0, sx1, sy1);
                *reinterpret_cast<float4*>(vs + (4 + g) * ROWB + o) =
                    make_float4(sp0, ss0, sp1, ss1);
            }
        }
        __syncthreads();

        // ---- Phase B: packed horizontal 7-sums + SSIM map ----
        {
            const int ty = tid >> 6, tx = tid & 63;
            const int rout = r + ty;
            if (rout < rend) {
                const char* rxy = vs + ty * ROWB;
                const char* rps = vs + (4 + ty) * ROWB;
                u64 fxy[16], fps[16];
#pragma unroll
                for (int i = 0; i < 8; i++) {
                    const int o = sw(tx * 64 + i * 16);
                    float4 t = *reinterpret_cast<const float4*>(rxy + o);
                    fxy[2 * i]     = f2pack(t.x, t.y);
                    fxy[2 * i + 1] = f2pack(t.z, t.w);
                    float4 u = *reinterpret_cast<const float4*>(rps + o);
                    fps[2 * i]     = f2pack(u.x, u.y);
                    fps[2 * i + 1] = f2pack(u.z, u.w);
                }
                u64 oxy[8], ops[8];
                {
                    u64 s1 = fxy[0], s2 = fps[0];
#pragma unroll
                    for (int j = 1; j <= 6; j++) { s1 = f2add(s1, fxy[j]); s2 = f2add(s2, fps[j]); }
                    oxy[0] = s1; ops[0] = s2;
#pragma unroll
                    for (int k = 1; k < 8; k++) {
                        s1 = f2add(s1, fxy[k + 6]); s1 = f2add(s1, f2neg(fxy[k - 1]));
                        s2 = f2add(s2, fps[k + 6]); s2 = f2add(s2, f2neg(fps[k - 1]));
                        oxy[k] = s1; ops[k] = s2;
                    }
                }
                const int cbase = 3 + tx * 8;
#pragma unroll
                for (int j = 0; j < 4; j++) {
                    const int k0 = 2 * j, k1 = 2 * j + 1;
                    float x0, y0, x1, y1, p0, s0, p1v, s1v;
                    f2unpack(oxy[k0], x0, y0); f2unpack(oxy[k1], x1, y1);
                    f2unpack(ops[k0], p0, s0); f2unpack(ops[k1], p1v, s1v);
                    u64 Ux = f2pack(x0, x1), Uy = f2pack(y0, y1);
                    u64 Up = f2pack(p0, p1v), Us = f2pack(s0, s1v);
                    u64 XY   = f2mul(Ux, Uy);
                    u64 X2Y2 = f2fma(Ux, Ux, f2mul(Uy, Uy));
                    u64 A1 = f2fma(two_2, XY, c1_2);
                    u64 A2 = f2fma(k2cn49, Up, f2fma(nk2cn, XY, c2_2));
                    u64 B1 = f2add(X2Y2, c1_2);
                    u64 B2 = f2fma(kcn49, Us, f2fma(nkcn, X2Y2, c2_2));
                    u64 num = f2mul(A1, A2), den = f2mul(B1, B2);
                    float n0, n1, d0, d1;
                    f2unpack(num, n0, n1); f2unpack(den, d0, d1);
                    float S0 = __fdividef(n0, d0);
                    float S1 = __fdividef(n1, d1);
                    if (cbase + k0 <= 508) acc += S0;
                    if (cbase + k1 <= 508) acc += S1;
                }
            }
        }
        __syncthreads();
    }

    // ---- block reduction ----
#pragma unroll
    for (int o = 16; o > 0; o >>= 1) acc += __shfl_down_sync(0xFFFFFFFFu, acc, o);
    if ((tid & 31) == 0) red[tid >> 5] = acc;
    __syncthreads();
    if (tid == 0) {
        float t = 0.f;
#pragma unroll
        for (int i = 0; i < 8; i++) t += red[i];
        g_partials[blockIdx.y * NBANDS + blockIdx.x] = t;
    }
}

__global__ void ssim_reduce(float* __restrict__ out) {
    __shared__ double red[24];
    const int tid = threadIdx.x;  // 768 threads
    double v = (double)g_partials[tid];
#pragma unroll
    for (int o = 16; o > 0; o >>= 1) v += __shfl_down_sync(0xFFFFFFFFu, v, o);
    if ((tid & 31) == 0) red[tid >> 5] = v;
    __syncthreads();
    if (tid == 0) {
        double t = 0.0;
#pragma unroll
        for (int i = 0; i < 24; i++) t += red[i];
        out[0] = (float)(t / (96.0 * 506.0 * 506.0));
    }
}

extern "C" void kernel_launch(void* const* d_in, const int* in_sizes, int n_in,
                              void* d_out, int out_size) {
    const float* img1 = (const float*)d_in[0];
    const float* img2 = (const float*)d_in[1];
    dim3 grid(NBANDS, NIMG);
    ssim_main<<<grid, 256>>>(img1, img2);
    ssim_reduce<<<1, NBANDS * NIMG>>>((float*)d_out);
}

// round 5
// speedup vs baseline: 2.0824x; 1.5473x over previous
#include <cuda_runtime.h>

typedef unsigned long long u64;

#define W 512
#define NIMG 96
#define WPI 24          // warps per image
#define BPI 6           // blocks per image (4 warps each)
#define RPW 22          // output rows per warp (24*22 = 528 >= 506)
#define FULLM 0xFFFFFFFFu

__device__ float g_partials[NIMG * WPI];

__device__ __forceinline__ u64 f2add(u64 a, u64 b) {
    u64 d; asm("add.rn.f32x2 %0, %1, %2;" : "=l"(d) : "l"(a), "l"(b)); return d;
}
__device__ __forceinline__ u64 f2fma(u64 a, u64 b, u64 c) {
    u64 d; asm("fma.rn.f32x2 %0, %1, %2, %3;" : "=l"(d) : "l"(a), "l"(b), "l"(c)); return d;
}
__device__ __forceinline__ u64 f2neg(u64 a) { return a ^ 0x8000000080000000ULL; }
__device__ __forceinline__ float flo(u64 a) {
    float x, y; asm("mov.b64 {%0, %1}, %2;" : "=f"(x), "=f"(y) : "l"(a)); return x;
}
__device__ __forceinline__ float fhi(u64 a) {
    float x, y; asm("mov.b64 {%0, %1}, %2;" : "=f"(x), "=f"(y) : "l"(a)); return y;
}

// element k of the extended vsum window [-3 .. 18] for one quantity.
// S[0..7] hold cols (0,1)..(14,15); l0,l1 = left lane's S[6],S[7] (cols 12..15);
// r0,r1 = right lane's S[0],S[1] (cols 16..19). k is compile-time constant.
__device__ __forceinline__ float elem(const u64* S, u64 l0, u64 l1, u64 r0, u64 r1, int k) {
    if (k == -3) return fhi(l0);
    if (k == -2) return flo(l1);
    if (k == -1) return fhi(l1);
    if (k == 16) return flo(r0);
    if (k == 17) return fhi(r0);
    if (k == 18) return flo(r1);
    u64 v = S[k >> 1];
    return (k & 1) ? fhi(v) : flo(v);
}

__global__ __launch_bounds__(128, 4) void ssim_main(const float* __restrict__ img1,
                                                    const float* __restrict__ img2) {
    const int lane = threadIdx.x & 31;
    const int wid  = threadIdx.x >> 5;                 // 0..3
    const int img  = blockIdx.x / BPI;
    const int wimg = (blockIdx.x % BPI) * 4 + wid;     // 0..23
    const int rs = 3 + wimg * RPW;
    const int re = min(rs + RPW, 509);

    const float* p1 = img1 + (size_t)img * (W * W);
    const float* p2 = img2 + (size_t)img * (W * W);
    const int c0 = lane * 16;

    u64 Sx[8], Sy[8], Sp[8], Ss[8];
#pragma unroll
    for (int i = 0; i < 8; i++) { Sx[i] = 0; Sy[i] = 0; Sp[i] = 0; Ss[i] = 0; }

#define ENTER(row) do {                                                          \
    const ulonglong2* qa = (const ulonglong2*)(p1 + (size_t)(row) * W + c0);     \
    const ulonglong2* qb = (const ulonglong2*)(p2 + (size_t)(row) * W + c0);     \
    _Pragma("unroll")                                                            \
    for (int i = 0; i < 4; i++) {                                                \
        ulonglong2 va = qa[i], vb = qb[i];                                       \
        u64 a0 = va.x, a1 = va.y, b0 = vb.x, b1 = vb.y;                          \
        Sx[2*i]   = f2add(Sx[2*i],   a0); Sx[2*i+1] = f2add(Sx[2*i+1], a1);      \
        Sy[2*i]   = f2add(Sy[2*i],   b0); Sy[2*i+1] = f2add(Sy[2*i+1], b1);      \
        Sp[2*i]   = f2fma(a0, b0, Sp[2*i]); Sp[2*i+1] = f2fma(a1, b1, Sp[2*i+1]);\
        Ss[2*i]   = f2fma(a0, a0, Ss[2*i]); Ss[2*i+1] = f2fma(a1, a1, Ss[2*i+1]);\
        Ss[2*i]   = f2fma(b0, b0, Ss[2*i]); Ss[2*i+1] = f2fma(b1, b1, Ss[2*i+1]);\
    }                                                                            \
} while (0)

#define EXITR(row) do {                                                          \
    const ulonglong2* qa = (const ulonglong2*)(p1 + (size_t)(row) * W + c0);     \
    const ulonglong2* qb = (const ulonglong2*)(p2 + (size_t)(row) * W + c0);     \
    _Pragma("unroll")                                                            \
    for (int i = 0; i < 4; i++) {                                                \
        ulonglong2 va = qa[i], vb = qb[i];                                       \
        u64 a0 = va.x, a1 = va.y, b0 = vb.x, b1 = vb.y;                          \
        u64 n0 = f2neg(a0), n1 = f2neg(a1), m0 = f2neg(b0), m1 = f2neg(b1);      \
        Sx[2*i]   = f2add(Sx[2*i],   n0); Sx[2*i+1] = f2add(Sx[2*i+1], n1);      \
        Sy[2*i]   = f2add(Sy[2*i],   m0); Sy[2*i+1] = f2add(Sy[2*i+1], m1);      \
        Sp[2*i]   = f2fma(n0, b0, Sp[2*i]); Sp[2*i+1] = f2fma(n1, b1, Sp[2*i+1]);\
        Ss[2*i]   = f2fma(n0, a0, Ss[2*i]); Ss[2*i+1] = f2fma(n1, a1, Ss[2*i+1]);\
        Ss[2*i]   = f2fma(m0, b0, Ss[2*i]); Ss[2*i+1] = f2fma(m1, b1, Ss[2*i+1]);\
    }                                                                            \
} while (0)

    // prime with rows rs-3 .. rs+2 (all in [0,511])
#pragma unroll 1
    for (int rr = rs - 3; rr < rs + 3; rr++) ENTER(rr);

    // scale-folded constants (window sums, not means; ratio unchanged)
    const float c1f = 1e-4f * 2401.0f;
    const float c2f = 9e-4f * 2401.0f;
    const float CNf = 49.0f / 48.0f;
    const float k2cn49 = 2.0f * CNf * 49.0f;
    const float nk2cn  = -2.0f * CNf;
    const float kcn49  = CNf * 49.0f;
    const float nkcn   = -CNf;

    float acc = 0.f;

#pragma unroll 1
    for (int r = rs; r < re; r++) {
        ENTER(r + 3);                 // r+3 <= 511
        if (r > rs) EXITR(r - 4);     // r-4 >= rs-3 >= 0

        // halo shuffles (whole warp participates)
        u64 lx0 = __shfl_up_sync(FULLM, Sx[6], 1), lx1 = __shfl_up_sync(FULLM, Sx[7], 1);
        u64 rx0 = __shfl_down_sync(FULLM, Sx[0], 1), rx1 = __shfl_down_sync(FULLM, Sx[1], 1);
        u64 ly0 = __shfl_up_sync(FULLM, Sy[6], 1), ly1 = __shfl_up_sync(FULLM, Sy[7], 1);
        u64 ry0 = __shfl_down_sync(FULLM, Sy[0], 1), ry1 = __shfl_down_sync(FULLM, Sy[1], 1);
        u64 lp0 = __shfl_up_sync(FULLM, Sp[6], 1), lp1 = __shfl_up_sync(FULLM, Sp[7], 1);
        u64 rp0 = __shfl_down_sync(FULLM, Sp[0], 1), rp1 = __shfl_down_sync(FULLM, Sp[1], 1);
        u64 ls0 = __shfl_up_sync(FULLM, Ss[6], 1), ls1 = __shfl_up_sync(FULLM, Ss[7], 1);
        u64 rs0 = __shfl_down_sync(FULLM, Ss[0], 1), rs1 = __shfl_down_sync(FULLM, Ss[1], 1);

#define EX(k) elem(Sx, lx0, lx1, rx0, rx1, (k))
#define EY(k) elem(Sy, ly0, ly1, ry0, ry1, (k))
#define EP(k) elem(Sp, lp0, lp1, rp0, rp1, (k))
#define ES(k) elem(Ss, ls0, ls1, rs0, rs1, (k))

        float hx = EX(-3) + EX(-2) + EX(-1) + EX(0) + EX(1) + EX(2) + EX(3);
        float hy = EY(-3) + EY(-2) + EY(-1) + EY(0) + EY(1) + EY(2) + EY(3);
        float hp = EP(-3) + EP(-2) + EP(-1) + EP(0) + EP(1) + EP(2) + EP(3);
        float hs = ES(-3) + ES(-2) + ES(-1) + ES(0) + ES(1) + ES(2) + ES(3);

#pragma unroll
        for (int k = 0; k < 16; k++) {
            if (k > 0) {
                hx += EX(k + 3) - EX(k - 4);
                hy += EY(k + 3) - EY(k - 4);
                hp += EP(k + 3) - EP(k - 4);
                hs += ES(k + 3) - ES(k - 4);
            }
            float XY = hx * hy;
            float X2 = fmaf(hx, hx, hy * hy);
            float A1 = fmaf(2.0f, XY, c1f);
            float A2 = fmaf(k2cn49, hp, fmaf(nk2cn, XY, c2f));
            float B1 = X2 + c1f;
            float B2 = fmaf(kcn49, hs, fmaf(nkcn, X2, c2f));
            float S  = __fdividef(A1 * A2, B1 * B2);
            int col = c0 + k;
            if (col >= 3 && col <= 508) acc += S;
        }
#undef EX
#undef EY
#undef EP
#undef ES
    }

    // warp reduction
#pragma unroll
    for (int o = 16; o > 0; o >>= 1) acc += __shfl_down_sync(FULLM, acc, o);
    if (lane == 0) g_partials[img * WPI + wimg] = acc;
}

__global__ void ssim_reduce(float* __restrict__ out) {
    __shared__ double red[18];
    const int tid = threadIdx.x;  // 576 threads
    double v = (double)g_partials[tid]
             + (double)g_partials[tid + 576]
             + (double)g_partials[tid + 1152]
             + (double)g_partials[tid + 1728];
#pragma unroll
    for (int o = 16; o > 0; o >>= 1) v += __shfl_down_sync(FULLM, v, o);
    if ((tid & 31) == 0) red[tid >> 5] = v;
    __syncthreads();
    if (tid == 0) {
        double t = 0.0;
#pragma unroll
        for (int i = 0; i < 18; i++) t += red[i];
        out[0] = (float)(t / (96.0 * 506.0 * 506.0));
    }
}

extern "C" void kernel_launch(void* const* d_in, const int* in_sizes, int n_in,
                              void* d_out, int out_size) {
    const float* img1 = (const float*)d_in[0];
    const float* img2 = (const float*)d_in[1];
    ssim_main<<<NIMG * BPI, 128>>>(img1, img2);
    ssim_reduce<<<1, 576>>>((float*)d_out);
}